// round 6
// baseline (speedup 1.0000x reference)
#include <cuda_runtime.h>
#include <cuda_bf16.h>
#include <mma.h>
#include <math.h>

using namespace nvcuda;

#define N_NODES 50000
#define N_EDGES 1600000
#define IN_F    256
#define OUT_F   128
#define ALPHA   0.2f
#define EPSV    1e-9f

// GEMM tiling
#define GBM 64
#define GBN 128
#define GBK 32
#define N_PAD 50048   // 782 blocks * 64 rows — padded so tail stores stay in-bounds

// ---------------- scratch (device globals; no allocations allowed) ----------
__device__ float g_h[(size_t)N_PAD * OUT_F];
__device__ float g_ssrc[N_NODES];
__device__ float g_sdst[N_NODES];
__device__ int   g_deg[N_NODES];
__device__ int   g_off[N_NODES + 1];
__device__ int   g_cursor[N_NODES];
__device__ int   g_dsts[N_EDGES];
__device__ float g_ws[N_EDGES];

// ---------------- GEMM: h = x @ W  (tf32 tensor cores) ----------------------
__global__ __launch_bounds__(256) void gemm_tf32_kernel(
    const float* __restrict__ x, const float* __restrict__ W,
    float* __restrict__ h, int N)
{
    __shared__ float As[GBM][GBK + 4];
    __shared__ float Bs[GBK][GBN];

    const int tid = threadIdx.x;
    const int wid = tid >> 5;
    const int wm = wid >> 1;
    const int wn = wid & 1;
    const int row0 = blockIdx.x * GBM;

    wmma::fragment<wmma::accumulator, 16, 16, 8, float> acc[4];
#pragma unroll
    for (int j = 0; j < 4; j++) wmma::fill_fragment(acc[j], 0.f);

    for (int k0 = 0; k0 < IN_F; k0 += GBK) {
#pragma unroll
        for (int i = 0; i < 2; i++) {
            const int f = tid + i * 256;
            const int r = f >> 3;
            const int c = (f & 7) * 4;
            int grow = row0 + r; if (grow >= N) grow = N - 1;
            *reinterpret_cast<float4*>(&As[r][c]) =
                *reinterpret_cast<const float4*>(x + (size_t)grow * IN_F + k0 + c);
        }
#pragma unroll
        for (int i = 0; i < 4; i++) {
            const int f = tid + i * 256;
            const int r = f >> 5;
            const int c = (f & 31) * 4;
            *reinterpret_cast<float4*>(&Bs[r][c]) =
                *reinterpret_cast<const float4*>(W + (size_t)(k0 + r) * GBN + c);
        }
        __syncthreads();

#pragma unroll
        for (int ks = 0; ks < GBK; ks += 8) {
            wmma::fragment<wmma::matrix_a, 16, 16, 8, wmma::precision::tf32, wmma::row_major> af;
            wmma::load_matrix_sync(af, &As[wm * 16][ks], GBK + 4);
#pragma unroll
            for (int t = 0; t < af.num_elements; t++) af.x[t] = wmma::__float_to_tf32(af.x[t]);
#pragma unroll
            for (int j = 0; j < 4; j++) {
                wmma::fragment<wmma::matrix_b, 16, 16, 8, wmma::precision::tf32, wmma::row_major> bf;
                wmma::load_matrix_sync(bf, &Bs[ks][wn * 64 + j * 16], GBN);
#pragma unroll
                for (int t = 0; t < bf.num_elements; t++) bf.x[t] = wmma::__float_to_tf32(bf.x[t]);
                wmma::mma_sync(acc[j], af, bf, acc[j]);
            }
        }
        __syncthreads();
    }

#pragma unroll
    for (int j = 0; j < 4; j++)
        wmma::store_matrix_sync(h + (size_t)(row0 + wm * 16) * OUT_F + wn * 64 + j * 16,
                                acc[j], OUT_F, wmma::mem_row_major);
}

// ---------------- per-node scores -------------------------------------------
__global__ __launch_bounds__(256) void score_kernel(
    const float* __restrict__ h, const float* __restrict__ a,
    float* __restrict__ ssrc, float* __restrict__ sdst, int N)
{
    const int warp = (blockIdx.x * blockDim.x + threadIdx.x) >> 5;
    const int lane = threadIdx.x & 31;
    if (warp >= N) return;

    const float4 hv = reinterpret_cast<const float4*>(h + (size_t)warp * OUT_F)[lane];
    const float4 as = reinterpret_cast<const float4*>(a)[lane];
    const float4 ad = reinterpret_cast<const float4*>(a + OUT_F)[lane];

    float s1 = hv.x * as.x + hv.y * as.y + hv.z * as.z + hv.w * as.w;
    float s2 = hv.x * ad.x + hv.y * ad.y + hv.z * ad.z + hv.w * ad.w;
#pragma unroll
    for (int o = 16; o > 0; o >>= 1) {
        s1 += __shfl_xor_sync(0xFFFFFFFFu, s1, o);
        s2 += __shfl_xor_sync(0xFFFFFFFFu, s2, o);
    }
    if (lane == 0) { ssrc[warp] = s1; sdst[warp] = s2; }
}

// ---------------- CSR build: histogram --------------------------------------
__global__ __launch_bounds__(256) void hist_kernel(
    const int* __restrict__ src, int* __restrict__ deg, int E)
{
    const int e = blockIdx.x * blockDim.x + threadIdx.x;
    if (e < E) atomicAdd(&deg[src[e]], 1);
}

// ---------------- CSR build: prefix scan (single block, 1024 threads) -------
__global__ __launch_bounds__(1024) void scan_kernel(
    const int* __restrict__ deg, int* __restrict__ off,
    int* __restrict__ cursor, int N, int E)
{
    __shared__ int part[1024];
    const int t = threadIdx.x;
    const int CH = (N + 1023) / 1024;
    const int base = t * CH;

    int s = 0;
    for (int i = 0; i < CH; i++) {
        const int idx = base + i;
        if (idx < N) s += deg[idx];
    }
    part[t] = s;
    __syncthreads();

    // Hillis-Steele inclusive scan
    for (int o = 1; o < 1024; o <<= 1) {
        const int v = (t >= o) ? part[t - o] : 0;
        __syncthreads();
        part[t] += v;
        __syncthreads();
    }
    int run = (t == 0) ? 0 : part[t - 1];

    for (int i = 0; i < CH; i++) {
        const int idx = base + i;
        if (idx < N) {
            off[idx] = run;
            cursor[idx] = run;
            run += deg[idx];
        }
    }
    if (t == 1023) off[N] = E;
}

// ---------------- CSR build: scatter + edge weights --------------------------
__global__ __launch_bounds__(256) void scatter_kernel(
    const int* __restrict__ src, const int* __restrict__ dst,
    const float* __restrict__ ssrc, const float* __restrict__ sdst,
    int* __restrict__ cursor, int* __restrict__ dsts, float* __restrict__ ws,
    int E)
{
    const int e = blockIdx.x * blockDim.x + threadIdx.x;
    if (e >= E) return;
    const int s = src[e];
    const int d = dst[e];
    const float sc = ssrc[s] + sdst[d];
    const float lr = sc >= 0.f ? sc : ALPHA * sc;
    const float w = __expf(-lr);
    const int pos = atomicAdd(&cursor[s], 1);
    dsts[pos] = d;
    ws[pos] = w;
}

// ---------------- aggregate: warp per node, registers, fused elu -------------
__global__ __launch_bounds__(256) void aggregate_kernel(
    const float4* __restrict__ h4, const int* __restrict__ off,
    const int* __restrict__ dsts, const float* __restrict__ ws,
    float4* __restrict__ out4, int N)
{
    const int warp = (blockIdx.x * blockDim.x + threadIdx.x) >> 5;
    const int lane = threadIdx.x & 31;
    if (warp >= N) return;

    const int beg = off[warp];
    const int end = off[warp + 1];

    float ax = 0.f, ay = 0.f, az = 0.f, aw = 0.f, wsum = 0.f;

    int i = beg;
    for (; i + 2 <= end; i += 2) {
        const int d0 = dsts[i];
        const int d1 = dsts[i + 1];
        const float w0 = ws[i];
        const float w1 = ws[i + 1];
        const float4 v0 = h4[(size_t)d0 * 32 + lane];
        const float4 v1 = h4[(size_t)d1 * 32 + lane];
        ax = fmaf(w0, v0.x, fmaf(w1, v1.x, ax));
        ay = fmaf(w0, v0.y, fmaf(w1, v1.y, ay));
        az = fmaf(w0, v0.z, fmaf(w1, v1.z, az));
        aw = fmaf(w0, v0.w, fmaf(w1, v1.w, aw));
        wsum += w0 + w1;
    }
    if (i < end) {
        const int d0 = dsts[i];
        const float w0 = ws[i];
        const float4 v0 = h4[(size_t)d0 * 32 + lane];
        ax = fmaf(w0, v0.x, ax);
        ay = fmaf(w0, v0.y, ay);
        az = fmaf(w0, v0.z, az);
        aw = fmaf(w0, v0.w, aw);
        wsum += w0;
    }

    const float r = 1.f / (wsum + EPSV);
    ax *= r; ay *= r; az *= r; aw *= r;
    ax = ax > 0.f ? ax : expm1f(ax);
    ay = ay > 0.f ? ay : expm1f(ay);
    az = az > 0.f ? az : expm1f(az);
    aw = aw > 0.f ? aw : expm1f(aw);
    out4[(size_t)warp * 32 + lane] = make_float4(ax, ay, az, aw);
}

// ---------------- launch ------------------------------------------------------
extern "C" void kernel_launch(void* const* d_in, const int* in_sizes, int n_in,
                              void* d_out, int out_size)
{
    const float* x  = (const float*)d_in[0];
    const int*   ei = (const int*)d_in[1];      // JAX x64 disabled -> int32
    const float* W  = (const float*)d_in[2];
    const float* a  = (const float*)d_in[3];
    float* out = (float*)d_out;

    const int N = in_sizes[0] / IN_F;        // 50000
    const int E = in_sizes[1] / 2;           // 1600000
    const int* src = ei;
    const int* dst = ei + E;

    float *h, *ssrc, *sdst, *ws;
    int *deg, *off, *cursor, *dsts;
    cudaGetSymbolAddress((void**)&h,      g_h);
    cudaGetSymbolAddress((void**)&ssrc,   g_ssrc);
    cudaGetSymbolAddress((void**)&sdst,   g_sdst);
    cudaGetSymbolAddress((void**)&deg,    g_deg);
    cudaGetSymbolAddress((void**)&off,    g_off);
    cudaGetSymbolAddress((void**)&cursor, g_cursor);
    cudaGetSymbolAddress((void**)&dsts,   g_dsts);
    cudaGetSymbolAddress((void**)&ws,     g_ws);

    cudaMemsetAsync(deg, 0, (size_t)N * sizeof(int), 0);

    // CSR histogram (only needs src)
    hist_kernel<<<(E + 255) / 256, 256>>>(src, deg, E);

    // h = x @ W (tf32 tensor cores)
    gemm_tf32_kernel<<<(N + GBM - 1) / GBM, 256>>>(x, W, h, N);

    // per-node scores
    score_kernel<<<(N + 7) / 8, 256>>>(h, a, ssrc, sdst, N);

    // prefix scan -> offsets + cursors
    scan_kernel<<<1, 1024>>>(deg, off, cursor, N, E);

    // scatter edges into CSR order + precompute weights
    scatter_kernel<<<(E + 255) / 256, 256>>>(src, dst, ssrc, sdst, cursor, dsts, ws, E);

    // aggregate per node (atomic-free) + fused elu
    aggregate_kernel<<<(N * 32 + 255) / 256, 256>>>(
        (const float4*)h, off, dsts, ws, (float4*)out, N);
}

// round 7
// speedup vs baseline: 1.2744x; 1.2744x over previous
#include <cuda_runtime.h>
#include <cuda_fp16.h>
#include <cuda_bf16.h>
#include <mma.h>
#include <math.h>

using namespace nvcuda;

#define N_NODES 50000
#define N_EDGES 1600000
#define IN_F    256
#define OUT_F   128
#define ALPHA   0.2f
#define EPSV    1e-9f

// GEMM tiling
#define GBM 64
#define GBN 128
#define GBK 32
#define N_PAD 50048

// scan config
#define SCAN_BS 256
#define SCAN_NB ((N_NODES + SCAN_BS - 1) / SCAN_BS)   // 196

// ---------------- scratch (device globals; no allocations allowed) ----------
__device__ float  g_h[(size_t)N_PAD * OUT_F];
__device__ __half g_hh[(size_t)N_NODES * OUT_F];
__device__ float  g_ssrc[N_NODES];
__device__ float  g_sdst[N_NODES];
__device__ int    g_deg[N_NODES];
__device__ int    g_off[N_NODES + 1];
__device__ int    g_cursor[N_NODES];
__device__ int    g_part[SCAN_NB];
__device__ int    g_dsts[N_EDGES];
__device__ float  g_ws[N_EDGES];

// ---------------- GEMM: h = x @ W  (tf32 tensor cores) ----------------------
__global__ __launch_bounds__(256) void gemm_tf32_kernel(
    const float* __restrict__ x, const float* __restrict__ W,
    float* __restrict__ h, int N)
{
    __shared__ float As[GBM][GBK + 4];
    __shared__ float Bs[GBK][GBN];

    const int tid = threadIdx.x;
    const int wid = tid >> 5;
    const int wm = wid >> 1;
    const int wn = wid & 1;
    const int row0 = blockIdx.x * GBM;

    wmma::fragment<wmma::accumulator, 16, 16, 8, float> acc[4];
#pragma unroll
    for (int j = 0; j < 4; j++) wmma::fill_fragment(acc[j], 0.f);

    for (int k0 = 0; k0 < IN_F; k0 += GBK) {
#pragma unroll
        for (int i = 0; i < 2; i++) {
            const int f = tid + i * 256;
            const int r = f >> 3;
            const int c = (f & 7) * 4;
            int grow = row0 + r; if (grow >= N) grow = N - 1;
            *reinterpret_cast<float4*>(&As[r][c]) =
                *reinterpret_cast<const float4*>(x + (size_t)grow * IN_F + k0 + c);
        }
#pragma unroll
        for (int i = 0; i < 4; i++) {
            const int f = tid + i * 256;
            const int r = f >> 5;
            const int c = (f & 31) * 4;
            *reinterpret_cast<float4*>(&Bs[r][c]) =
                *reinterpret_cast<const float4*>(W + (size_t)(k0 + r) * GBN + c);
        }
        __syncthreads();

#pragma unroll
        for (int ks = 0; ks < GBK; ks += 8) {
            wmma::fragment<wmma::matrix_a, 16, 16, 8, wmma::precision::tf32, wmma::row_major> af;
            wmma::load_matrix_sync(af, &As[wm * 16][ks], GBK + 4);
#pragma unroll
            for (int t = 0; t < af.num_elements; t++) af.x[t] = wmma::__float_to_tf32(af.x[t]);
#pragma unroll
            for (int j = 0; j < 4; j++) {
                wmma::fragment<wmma::matrix_b, 16, 16, 8, wmma::precision::tf32, wmma::row_major> bf;
                wmma::load_matrix_sync(bf, &Bs[ks][wn * 64 + j * 16], GBN);
#pragma unroll
                for (int t = 0; t < bf.num_elements; t++) bf.x[t] = wmma::__float_to_tf32(bf.x[t]);
                wmma::mma_sync(acc[j], af, bf, acc[j]);
            }
        }
        __syncthreads();
    }

#pragma unroll
    for (int j = 0; j < 4; j++)
        wmma::store_matrix_sync(h + (size_t)(row0 + wm * 16) * OUT_F + wn * 64 + j * 16,
                                acc[j], OUT_F, wmma::mem_row_major);
}

// ---------------- per-node scores + fp16 mirror of h --------------------------
__global__ __launch_bounds__(256) void score_kernel(
    const float* __restrict__ h, const float* __restrict__ a,
    float* __restrict__ ssrc, float* __restrict__ sdst,
    __half* __restrict__ hh, int N)
{
    const int warp = (blockIdx.x * blockDim.x + threadIdx.x) >> 5;
    const int lane = threadIdx.x & 31;
    if (warp >= N) return;

    const float4 hv = reinterpret_cast<const float4*>(h + (size_t)warp * OUT_F)[lane];
    const float4 as = reinterpret_cast<const float4*>(a)[lane];
    const float4 ad = reinterpret_cast<const float4*>(a + OUT_F)[lane];

    // fp16 mirror: 4 halves per lane (uint2 store)
    __half2 p0 = __floats2half2_rn(hv.x, hv.y);
    __half2 p1 = __floats2half2_rn(hv.z, hv.w);
    reinterpret_cast<__half2*>(hh + (size_t)warp * OUT_F)[lane * 2]     = p0;
    reinterpret_cast<__half2*>(hh + (size_t)warp * OUT_F)[lane * 2 + 1] = p1;

    float s1 = hv.x * as.x + hv.y * as.y + hv.z * as.z + hv.w * as.w;
    float s2 = hv.x * ad.x + hv.y * ad.y + hv.z * ad.z + hv.w * ad.w;
#pragma unroll
    for (int o = 16; o > 0; o >>= 1) {
        s1 += __shfl_xor_sync(0xFFFFFFFFu, s1, o);
        s2 += __shfl_xor_sync(0xFFFFFFFFu, s2, o);
    }
    if (lane == 0) { ssrc[warp] = s1; sdst[warp] = s2; }
}

// ---------------- CSR build: histogram --------------------------------------
__global__ __launch_bounds__(256) void hist_kernel(
    const int* __restrict__ src, int* __restrict__ deg, int E)
{
    const int e = blockIdx.x * blockDim.x + threadIdx.x;
    if (e < E) atomicAdd(&deg[src[e]], 1);
}

// ---------------- scan phase 1: per-block sums --------------------------------
__global__ __launch_bounds__(SCAN_BS) void scan1_kernel(
    const int* __restrict__ deg, int* __restrict__ part, int N)
{
    __shared__ int sh[SCAN_BS];
    const int idx = blockIdx.x * SCAN_BS + threadIdx.x;
    int v = (idx < N) ? deg[idx] : 0;
    sh[threadIdx.x] = v;
    __syncthreads();
#pragma unroll
    for (int o = SCAN_BS / 2; o > 0; o >>= 1) {
        if (threadIdx.x < o) sh[threadIdx.x] += sh[threadIdx.x + o];
        __syncthreads();
    }
    if (threadIdx.x == 0) part[blockIdx.x] = sh[0];
}

// ---------------- scan phase 2: exclusive scan of partials (1 block) ----------
__global__ __launch_bounds__(SCAN_BS) void scan2_kernel(int* __restrict__ part)
{
    __shared__ int sh[SCAN_BS];
    const int t = threadIdx.x;
    int v = (t < SCAN_NB) ? part[t] : 0;
    sh[t] = v;
    __syncthreads();
#pragma unroll
    for (int o = 1; o < SCAN_BS; o <<= 1) {
        int u = (t >= o) ? sh[t - o] : 0;
        __syncthreads();
        sh[t] += u;
        __syncthreads();
    }
    if (t < SCAN_NB) part[t] = sh[t] - v;   // exclusive
}

// ---------------- scan phase 3: local scan + write offsets --------------------
__global__ __launch_bounds__(SCAN_BS) void scan3_kernel(
    const int* __restrict__ deg, const int* __restrict__ part,
    int* __restrict__ off, int* __restrict__ cursor, int N, int E)
{
    __shared__ int sh[SCAN_BS];
    const int t = threadIdx.x;
    const int idx = blockIdx.x * SCAN_BS + t;
    int v = (idx < N) ? deg[idx] : 0;
    sh[t] = v;
    __syncthreads();
#pragma unroll
    for (int o = 1; o < SCAN_BS; o <<= 1) {
        int u = (t >= o) ? sh[t - o] : 0;
        __syncthreads();
        sh[t] += u;
        __syncthreads();
    }
    if (idx < N) {
        const int o = part[blockIdx.x] + sh[t] - v;   // exclusive global prefix
        off[idx] = o;
        cursor[idx] = o;
        if (idx == N - 1) off[N] = E;
    }
}

// ---------------- CSR build: scatter + edge weights --------------------------
__global__ __launch_bounds__(256) void scatter_kernel(
    const int* __restrict__ src, const int* __restrict__ dst,
    const float* __restrict__ ssrc, const float* __restrict__ sdst,
    int* __restrict__ cursor, int* __restrict__ dsts, float* __restrict__ ws,
    int E)
{
    const int e = blockIdx.x * blockDim.x + threadIdx.x;
    if (e >= E) return;
    const int s = src[e];
    const int d = dst[e];
    const float sc = ssrc[s] + sdst[d];
    const float lr = sc >= 0.f ? sc : ALPHA * sc;
    const float w = __expf(-lr);
    const int pos = atomicAdd(&cursor[s], 1);
    dsts[pos] = d;
    ws[pos] = w;
}

// ---------------- aggregate: warp per node, fp16 gather, fused elu -----------
__global__ __launch_bounds__(256) void aggregate_kernel(
    const uint2* __restrict__ hh2, const int* __restrict__ off,
    const int* __restrict__ dsts, const float* __restrict__ ws,
    float4* __restrict__ out4, int N)
{
    const int warp = (blockIdx.x * blockDim.x + threadIdx.x) >> 5;
    const int lane = threadIdx.x & 31;
    if (warp >= N) return;

    const int beg = off[warp];
    const int end = off[warp + 1];

    float ax = 0.f, ay = 0.f, az = 0.f, aw = 0.f, wsum = 0.f;

    int i = beg;
    for (; i + 4 <= end; i += 4) {
        int   d0 = dsts[i],   d1 = dsts[i+1], d2 = dsts[i+2], d3 = dsts[i+3];
        float w0 = ws[i],     w1 = ws[i+1],   w2 = ws[i+2],   w3 = ws[i+3];
        const uint2 u0 = hh2[(size_t)d0 * 32 + lane];
        const uint2 u1 = hh2[(size_t)d1 * 32 + lane];
        const uint2 u2 = hh2[(size_t)d2 * 32 + lane];
        const uint2 u3 = hh2[(size_t)d3 * 32 + lane];
        float2 a0 = __half22float2(*(const __half2*)&u0.x), b0 = __half22float2(*(const __half2*)&u0.y);
        float2 a1 = __half22float2(*(const __half2*)&u1.x), b1 = __half22float2(*(const __half2*)&u1.y);
        float2 a2 = __half22float2(*(const __half2*)&u2.x), b2 = __half22float2(*(const __half2*)&u2.y);
        float2 a3 = __half22float2(*(const __half2*)&u3.x), b3 = __half22float2(*(const __half2*)&u3.y);
        ax = fmaf(w0, a0.x, fmaf(w1, a1.x, fmaf(w2, a2.x, fmaf(w3, a3.x, ax))));
        ay = fmaf(w0, a0.y, fmaf(w1, a1.y, fmaf(w2, a2.y, fmaf(w3, a3.y, ay))));
        az = fmaf(w0, b0.x, fmaf(w1, b1.x, fmaf(w2, b2.x, fmaf(w3, b3.x, az))));
        aw = fmaf(w0, b0.y, fmaf(w1, b1.y, fmaf(w2, b2.y, fmaf(w3, b3.y, aw))));
        wsum += (w0 + w1) + (w2 + w3);
    }
    for (; i < end; i++) {
        const int d0 = dsts[i];
        const float w0 = ws[i];
        const uint2 u0 = hh2[(size_t)d0 * 32 + lane];
        float2 a0 = __half22float2(*(const __half2*)&u0.x), b0 = __half22float2(*(const __half2*)&u0.y);
        ax = fmaf(w0, a0.x, ax);
        ay = fmaf(w0, a0.y, ay);
        az = fmaf(w0, b0.x, az);
        aw = fmaf(w0, b0.y, aw);
        wsum += w0;
    }

    const float r = 1.f / (wsum + EPSV);
    ax *= r; ay *= r; az *= r; aw *= r;
    ax = ax > 0.f ? ax : expm1f(ax);
    ay = ay > 0.f ? ay : expm1f(ay);
    az = az > 0.f ? az : expm1f(az);
    aw = aw > 0.f ? aw : expm1f(aw);
    out4[(size_t)warp * 32 + lane] = make_float4(ax, ay, az, aw);
}

// ---------------- launch ------------------------------------------------------
extern "C" void kernel_launch(void* const* d_in, const int* in_sizes, int n_in,
                              void* d_out, int out_size)
{
    const float* x  = (const float*)d_in[0];
    const int*   ei = (const int*)d_in[1];      // JAX x64 disabled -> int32
    const float* W  = (const float*)d_in[2];
    const float* a  = (const float*)d_in[3];
    float* out = (float*)d_out;

    const int N = in_sizes[0] / IN_F;        // 50000
    const int E = in_sizes[1] / 2;           // 1600000
    const int* src = ei;
    const int* dst = ei + E;

    float *h, *ssrc, *sdst, *ws;
    __half* hh;
    int *deg, *off, *cursor, *part, *dsts;
    cudaGetSymbolAddress((void**)&h,      g_h);
    cudaGetSymbolAddress((void**)&hh,     g_hh);
    cudaGetSymbolAddress((void**)&ssrc,   g_ssrc);
    cudaGetSymbolAddress((void**)&sdst,   g_sdst);
    cudaGetSymbolAddress((void**)&deg,    g_deg);
    cudaGetSymbolAddress((void**)&off,    g_off);
    cudaGetSymbolAddress((void**)&cursor, g_cursor);
    cudaGetSymbolAddress((void**)&part,   g_part);
    cudaGetSymbolAddress((void**)&dsts,   g_dsts);
    cudaGetSymbolAddress((void**)&ws,     g_ws);

    cudaMemsetAsync(deg, 0, (size_t)N * sizeof(int), 0);

    // CSR histogram
    hist_kernel<<<(E + 255) / 256, 256>>>(src, deg, E);

    // 3-phase parallel exclusive scan
    scan1_kernel<<<SCAN_NB, SCAN_BS>>>(deg, part, N);
    scan2_kernel<<<1, SCAN_BS>>>(part);
    scan3_kernel<<<SCAN_NB, SCAN_BS>>>(deg, part, off, cursor, N, E);

    // h = x @ W (tf32 tensor cores)
    gemm_tf32_kernel<<<(N + GBM - 1) / GBM, 256>>>(x, W, h, N);

    // per-node scores + fp16 mirror
    score_kernel<<<(N + 7) / 8, 256>>>(h, a, ssrc, sdst, hh, N);

    // scatter edges into CSR order + precompute weights
    scatter_kernel<<<(E + 255) / 256, 256>>>(src, dst, ssrc, sdst, cursor, dsts, ws, E);

    // aggregate per node (atomic-free, fp16 gather) + fused elu
    aggregate_kernel<<<(N * 32 + 255) / 256, 256>>>(
        (const uint2*)hh, off, dsts, ws, (float4*)out, N);
}

// round 9
// speedup vs baseline: 1.5644x; 1.2276x over previous
#include <cuda_runtime.h>
#include <cuda_fp16.h>
#include <cuda_bf16.h>
#include <mma.h>
#include <math.h>

using namespace nvcuda;

#define N_NODES 50000
#define N_EDGES 1600000
#define IN_F    256
#define OUT_F   128
#define ALPHA   0.2f
#define EPSV    1e-9f

// GEMM tiling: 128x128 block tile, BK=16, double-buffered smem
#define GBM 128
#define GBN 128
#define GBK 16
#define N_PAD 50048   // 391 blocks * 128 rows

// scan config
#define SCAN_BS 256
#define SCAN_NB ((N_NODES + SCAN_BS - 1) / SCAN_BS)   // 196

// ---------------- scratch (device globals; no allocations allowed) ----------
__device__ float  g_h[(size_t)N_PAD * OUT_F];
__device__ __half g_hh[(size_t)N_NODES * OUT_F];
__device__ float  g_ssrc[N_NODES];
__device__ float  g_sdst[N_NODES];
__device__ int    g_deg[N_NODES];
__device__ int    g_off[N_NODES + 1];
__device__ int    g_cursor[N_NODES];
__device__ int    g_part[SCAN_NB];
__device__ int2   g_edge[N_EDGES];    // packed (dst, w bits)

// ---------------- GEMM: h = x @ W  (tf32, double-buffered) ------------------
__global__ __launch_bounds__(256) void gemm_tf32_kernel(
    const float* __restrict__ x, const float* __restrict__ W,
    float* __restrict__ h, int N)
{
    __shared__ float As[2][GBM][GBK + 4];   // 2*128*20*4 = 20.5 KB
    __shared__ float Bs[2][GBK][GBN];       // 2*16*128*4 = 16 KB

    const int tid = threadIdx.x;
    const int wid = tid >> 5;
    const int wm = wid >> 2;       // 0..1 -> 64 rows each
    const int wn = wid & 3;        // 0..3 -> 32 cols each
    const int row0 = blockIdx.x * GBM;

    // load indices: A 128x16 = 512 float4, 2/thread; B 16x128 = 512 float4, 2/thread
    const int ar0 = tid >> 2;            // +0, +64 rows (i*64)
    const int ac  = (tid & 3) * 4;
    const int br0 = tid >> 5;            // +0, +8 rows
    const int bc  = (tid & 31) * 4;

    wmma::fragment<wmma::accumulator, 16, 16, 8, float> acc[4][2];
#pragma unroll
    for (int i = 0; i < 4; i++)
#pragma unroll
        for (int j = 0; j < 2; j++) wmma::fill_fragment(acc[i][j], 0.f);

    // preload chunk 0 into buffer 0
    {
#pragma unroll
        for (int i = 0; i < 2; i++) {
            int grow = row0 + ar0 + i * 64; if (grow >= N) grow = N - 1;
            *reinterpret_cast<float4*>(&As[0][ar0 + i * 64][ac]) =
                *reinterpret_cast<const float4*>(x + (size_t)grow * IN_F + ac);
            *reinterpret_cast<float4*>(&Bs[0][br0 + i * 8][bc]) =
                *reinterpret_cast<const float4*>(W + (size_t)(br0 + i * 8) * GBN + bc);
        }
    }
    __syncthreads();

    const int NIT = IN_F / GBK;   // 16
    for (int it = 0; it < NIT; it++) {
        const int cur = it & 1;
        float4 a_reg[2], b_reg[2];
        if (it + 1 < NIT) {
            const int k0 = (it + 1) * GBK;
#pragma unroll
            for (int i = 0; i < 2; i++) {
                int grow = row0 + ar0 + i * 64; if (grow >= N) grow = N - 1;
                a_reg[i] = *reinterpret_cast<const float4*>(x + (size_t)grow * IN_F + k0 + ac);
                b_reg[i] = *reinterpret_cast<const float4*>(W + (size_t)(k0 + br0 + i * 8) * GBN + bc);
            }
        }

#pragma unroll
        for (int ks = 0; ks < 2; ks++) {
            wmma::fragment<wmma::matrix_a, 16, 16, 8, wmma::precision::tf32, wmma::row_major> af[4];
#pragma unroll
            for (int mt = 0; mt < 4; mt++) {
                wmma::load_matrix_sync(af[mt], &As[cur][wm * 64 + mt * 16][ks * 8], GBK + 4);
#pragma unroll
                for (int t = 0; t < af[mt].num_elements; t++)
                    af[mt].x[t] = wmma::__float_to_tf32(af[mt].x[t]);
            }
#pragma unroll
            for (int nt = 0; nt < 2; nt++) {
                wmma::fragment<wmma::matrix_b, 16, 16, 8, wmma::precision::tf32, wmma::row_major> bf;
                wmma::load_matrix_sync(bf, &Bs[cur][ks * 8][wn * 32 + nt * 16], GBN);
#pragma unroll
                for (int t = 0; t < bf.num_elements; t++)
                    bf.x[t] = wmma::__float_to_tf32(bf.x[t]);
#pragma unroll
                for (int mt = 0; mt < 4; mt++)
                    wmma::mma_sync(acc[mt][nt], af[mt], bf, acc[mt][nt]);
            }
        }

        if (it + 1 < NIT) {
            const int nxt = 1 - cur;
#pragma unroll
            for (int i = 0; i < 2; i++) {
                *reinterpret_cast<float4*>(&As[nxt][ar0 + i * 64][ac]) = a_reg[i];
                *reinterpret_cast<float4*>(&Bs[nxt][br0 + i * 8][bc]) = b_reg[i];
            }
            __syncthreads();
        }
    }

#pragma unroll
    for (int mt = 0; mt < 4; mt++)
#pragma unroll
        for (int nt = 0; nt < 2; nt++)
            wmma::store_matrix_sync(
                h + (size_t)(row0 + wm * 64 + mt * 16) * OUT_F + wn * 32 + nt * 16,
                acc[mt][nt], OUT_F, wmma::mem_row_major);
}

// ---------------- per-node scores + fp16 mirror of h --------------------------
__global__ __launch_bounds__(256) void score_kernel(
    const float* __restrict__ h, const float* __restrict__ a,
    float* __restrict__ ssrc, float* __restrict__ sdst,
    __half* __restrict__ hh, int N)
{
    const int warp = (blockIdx.x * blockDim.x + threadIdx.x) >> 5;
    const int lane = threadIdx.x & 31;
    if (warp >= N) return;

    const float4 hv = reinterpret_cast<const float4*>(h + (size_t)warp * OUT_F)[lane];
    const float4 as = reinterpret_cast<const float4*>(a)[lane];
    const float4 ad = reinterpret_cast<const float4*>(a + OUT_F)[lane];

    __half2 p0 = __floats2half2_rn(hv.x, hv.y);
    __half2 p1 = __floats2half2_rn(hv.z, hv.w);
    reinterpret_cast<__half2*>(hh + (size_t)warp * OUT_F)[lane * 2]     = p0;
    reinterpret_cast<__half2*>(hh + (size_t)warp * OUT_F)[lane * 2 + 1] = p1;

    float s1 = hv.x * as.x + hv.y * as.y + hv.z * as.z + hv.w * as.w;
    float s2 = hv.x * ad.x + hv.y * ad.y + hv.z * ad.z + hv.w * ad.w;
#pragma unroll
    for (int o = 16; o > 0; o >>= 1) {
        s1 += __shfl_xor_sync(0xFFFFFFFFu, s1, o);
        s2 += __shfl_xor_sync(0xFFFFFFFFu, s2, o);
    }
    if (lane == 0) { ssrc[warp] = s1; sdst[warp] = s2; }
}

// ---------------- CSR build: histogram --------------------------------------
__global__ __launch_bounds__(256) void hist_kernel(
    const int* __restrict__ src, int* __restrict__ deg, int E)
{
    const int e = blockIdx.x * blockDim.x + threadIdx.x;
    if (e < E) atomicAdd(&deg[src[e]], 1);
}

// ---------------- scan phase 1: per-block sums --------------------------------
__global__ __launch_bounds__(SCAN_BS) void scan1_kernel(
    const int* __restrict__ deg, int* __restrict__ part, int N)
{
    __shared__ int sh[SCAN_BS];
    const int idx = blockIdx.x * SCAN_BS + threadIdx.x;
    int v = (idx < N) ? deg[idx] : 0;
    sh[threadIdx.x] = v;
    __syncthreads();
#pragma unroll
    for (int o = SCAN_BS / 2; o > 0; o >>= 1) {
        if (threadIdx.x < o) sh[threadIdx.x] += sh[threadIdx.x + o];
        __syncthreads();
    }
    if (threadIdx.x == 0) part[blockIdx.x] = sh[0];
}

// ---------------- scan phase 2: exclusive scan of partials (1 block) ----------
__global__ __launch_bounds__(SCAN_BS) void scan2_kernel(int* __restrict__ part)
{
    __shared__ int sh[SCAN_BS];
    const int t = threadIdx.x;
    int v = (t < SCAN_NB) ? part[t] : 0;
    sh[t] = v;
    __syncthreads();
#pragma unroll
    for (int o = 1; o < SCAN_BS; o <<= 1) {
        int u = (t >= o) ? sh[t - o] : 0;
        __syncthreads();
        sh[t] += u;
        __syncthreads();
    }
    if (t < SCAN_NB) part[t] = sh[t] - v;
}

// ---------------- scan phase 3: local scan + write offsets --------------------
__global__ __launch_bounds__(SCAN_BS) void scan3_kernel(
    const int* __restrict__ deg, const int* __restrict__ part,
    int* __restrict__ off, int* __restrict__ cursor, int N, int E)
{
    __shared__ int sh[SCAN_BS];
    const int t = threadIdx.x;
    const int idx = blockIdx.x * SCAN_BS + t;
    int v = (idx < N) ? deg[idx] : 0;
    sh[t] = v;
    __syncthreads();
#pragma unroll
    for (int o = 1; o < SCAN_BS; o <<= 1) {
        int u = (t >= o) ? sh[t - o] : 0;
        __syncthreads();
        sh[t] += u;
        __syncthreads();
    }
    if (idx < N) {
        const int o = part[blockIdx.x] + sh[t] - v;
        off[idx] = o;
        cursor[idx] = o;
        if (idx == N - 1) off[N] = E;
    }
}

// ---------------- CSR build: scatter + edge weights (packed int2) -------------
__global__ __launch_bounds__(256) void scatter_kernel(
    const int* __restrict__ src, const int* __restrict__ dst,
    const float* __restrict__ ssrc, const float* __restrict__ sdst,
    int* __restrict__ cursor, int2* __restrict__ edge, int E)
{
    const int e = blockIdx.x * blockDim.x + threadIdx.x;
    if (e >= E) return;
    const int s = src[e];
    const int d = dst[e];
    const float sc = ssrc[s] + sdst[d];
    const float lr = sc >= 0.f ? sc : ALPHA * sc;
    const float w = __expf(-lr);
    const int pos = atomicAdd(&cursor[s], 1);
    edge[pos] = make_int2(d, __float_as_int(w));
}

// ---------------- aggregate: warp per node, unroll 8, fused elu ---------------
__global__ __launch_bounds__(512) void aggregate_kernel(
    const uint2* __restrict__ hh2, const int* __restrict__ off,
    const uint2* __restrict__ edge, float4* __restrict__ out4, int N)
{
    const int warp = (blockIdx.x * blockDim.x + threadIdx.x) >> 5;
    const int lane = threadIdx.x & 31;
    if (warp >= N) return;

    const int beg = off[warp];
    const int end = off[warp + 1];

    float ax = 0.f, ay = 0.f, az = 0.f, aw = 0.f, wsum = 0.f;

    int i = beg;
    for (; i + 8 <= end; i += 8) {
        uint2 ed[8]; uint2 u[8];
#pragma unroll
        for (int j = 0; j < 8; j++) ed[j] = edge[i + j];
#pragma unroll
        for (int j = 0; j < 8; j++) u[j] = hh2[(size_t)ed[j].x * 32 + lane];
#pragma unroll
        for (int j = 0; j < 8; j++) {
            const float w = __int_as_float((int)ed[j].y);
            float2 lo = __half22float2(*(const __half2*)&u[j].x);
            float2 hi = __half22float2(*(const __half2*)&u[j].y);
            ax = fmaf(w, lo.x, ax);
            ay = fmaf(w, lo.y, ay);
            az = fmaf(w, hi.x, az);
            aw = fmaf(w, hi.y, aw);
            wsum += w;
        }
    }
    for (; i < end; i++) {
        const uint2 ed = edge[i];
        const float w = __int_as_float((int)ed.y);
        const uint2 u = hh2[(size_t)ed.x * 32 + lane];
        float2 lo = __half22float2(*(const __half2*)&u.x);
        float2 hi = __half22float2(*(const __half2*)&u.y);
        ax = fmaf(w, lo.x, ax);
        ay = fmaf(w, lo.y, ay);
        az = fmaf(w, hi.x, az);
        aw = fmaf(w, hi.y, aw);
        wsum += w;
    }

    const float r = 1.f / (wsum + EPSV);
    ax *= r; ay *= r; az *= r; aw *= r;
    ax = ax > 0.f ? ax : expm1f(ax);
    ay = ay > 0.f ? ay : expm1f(ay);
    az = az > 0.f ? az : expm1f(az);
    aw = aw > 0.f ? aw : expm1f(aw);
    out4[(size_t)warp * 32 + lane] = make_float4(ax, ay, az, aw);
}

// ---------------- launch ------------------------------------------------------
extern "C" void kernel_launch(void* const* d_in, const int* in_sizes, int n_in,
                              void* d_out, int out_size)
{
    const float* x  = (const float*)d_in[0];
    const int*   ei = (const int*)d_in[1];      // JAX x64 disabled -> int32
    const float* W  = (const float*)d_in[2];
    const float* a  = (const float*)d_in[3];
    float* out = (float*)d_out;

    const int N = in_sizes[0] / IN_F;        // 50000
    const int E = in_sizes[1] / 2;           // 1600000
    const int* src = ei;
    const int* dst = ei + E;

    float *h, *ssrc, *sdst;
    __half* hh;
    int *deg, *off, *cursor, *part;
    int2* edge;
    cudaGetSymbolAddress((void**)&h,      g_h);
    cudaGetSymbolAddress((void**)&hh,     g_hh);
    cudaGetSymbolAddress((void**)&ssrc,   g_ssrc);
    cudaGetSymbolAddress((void**)&sdst,   g_sdst);
    cudaGetSymbolAddress((void**)&deg,    g_deg);
    cudaGetSymbolAddress((void**)&off,    g_off);
    cudaGetSymbolAddress((void**)&cursor, g_cursor);
    cudaGetSymbolAddress((void**)&part,   g_part);
    cudaGetSymbolAddress((void**)&edge,   g_edge);

    cudaMemsetAsync(deg, 0, (size_t)N * sizeof(int), 0);

    // CSR histogram
    hist_kernel<<<(E + 255) / 256, 256>>>(src, deg, E);

    // 3-phase parallel exclusive scan
    scan1_kernel<<<SCAN_NB, SCAN_BS>>>(deg, part, N);
    scan2_kernel<<<1, SCAN_BS>>>(part);
    scan3_kernel<<<SCAN_NB, SCAN_BS>>>(deg, part, off, cursor, N, E);

    // h = x @ W (tf32 tensor cores, double-buffered)
    gemm_tf32_kernel<<<(N + GBM - 1) / GBM, 256>>>(x, W, h, N);

    // per-node scores + fp16 mirror
    score_kernel<<<(N + 7) / 8, 256>>>(h, a, ssrc, sdst, hh, N);

    // scatter edges into CSR order + precompute weights (packed)
    scatter_kernel<<<(E + 255) / 256, 256>>>(src, dst, ssrc, sdst, cursor, edge, E);

    // aggregate per node (atomic-free, fp16 gather, unroll 8) + fused elu
    aggregate_kernel<<<(N * 32 + 511) / 512, 512>>>(
        (const uint2*)hh, off, (const uint2*)edge, (float4*)out, N);
}